// round 7
// baseline (speedup 1.0000x reference)
#include <cuda_runtime.h>
#include <cstdint>

constexpr int B_ = 8192;
constexpr int K_ = 32;
constexpr int D_ = 129;
constexpr int V_ = 2048;
constexpr int KTOP = 10;
constexpr float WEIGHT_ = 0.15f;
constexpr int WARPS_PER_BLK = 4;
constexpr int BLOCKS = B_ / WARPS_PER_BLK;          // 2048
// tile layout (floats): [0..129) anchor | [132..261) positive | [264..4392) negatives
constexpr int OFF_POS = 132;
constexpr int OFF_NEG = 264;                        // byte 1056, 16B-aligned
constexpr int TILE_PAD = OFF_NEG + K_ * D_;         // 4392 floats = 17568 B (16B mult)
constexpr int SMEM_BYTES = WARPS_PER_BLK * TILE_PAD * 4;  // 70272

__device__ float g_part[BLOCKS];
__device__ int   g_count = 0;

__device__ __forceinline__ float warp_sum(float v) {
#pragma unroll
    for (int o = 16; o; o >>= 1) v += __shfl_xor_sync(0xffffffffu, v, o);
    return v;
}
__device__ __forceinline__ float warp_max(float v) {
#pragma unroll
    for (int o = 16; o; o >>= 1) v = fmaxf(v, __shfl_xor_sync(0xffffffffu, v, o));
    return v;
}
__device__ __forceinline__ float acoshd(float x) {
    x = fmaxf(x, 1.0f + 1e-7f);
    return logf(x + sqrtf(x * x - 1.0f));
}
__device__ __forceinline__ float pair_term(float ri, float ci, float di,
                                           float rj, float cj, float dj,
                                           float inv_idcg) {
    float drel  = ri - rj;
    float delta = fabsf(drel * (ci - cj)) * inv_idcg;
    float dd    = dj - di;
    float s     = (drel > 0.0f) ? 1.0f : -1.0f;
    float x     = s * dd;
    float sig   = __fdividef(1.0f, 1.0f + __expf(-x));
    return s * delta * sig * (-dd);
}
__device__ __forceinline__ void cpa16(uint32_t s, const void* g) {
    asm volatile("cp.async.cg.shared.global [%0], [%1], 16;" :: "r"(s), "l"(g));
}
__device__ __forceinline__ void cpa4(uint32_t s, const void* g) {
    asm volatile("cp.async.ca.shared.global [%0], [%1], 4;" :: "r"(s), "l"(g));
}

__global__ void __launch_bounds__(128) lr_fused(
    const float* __restrict__ anchor,
    const float* __restrict__ positive,
    const float* __restrict__ negative,
    const float* __restrict__ tree,
    const int*   __restrict__ aidx,
    const int*   __restrict__ pidx,
    const int*   __restrict__ nidx,
    float*       __restrict__ out)
{
    extern __shared__ float smem[];
    __shared__ float s_warp[WARPS_PER_BLK];
    __shared__ float s_fin[128];
    __shared__ bool  s_last;

    const int w    = threadIdx.x >> 5;
    const int lane = threadIdx.x & 31;
    const int b    = blockIdx.x * WARPS_PER_BLK + w;

    float* tw = smem + w * TILE_PAD;
    const uint32_t tw_s = (uint32_t)__cvta_generic_to_shared(tw);

    const float* __restrict__ arow = anchor   + (size_t)b * D_;
    const float* __restrict__ pb   = positive + (size_t)b * D_;
    const float* __restrict__ nb   = negative + (size_t)b * K_ * D_;

    // ===== stage row tile into smem via cp.async =====
#pragma unroll
    for (int k = lane; k < D_; k += 32) {
        cpa4(tw_s + 4u * k,              arow + k);
        cpa4(tw_s + 4u * (OFF_POS + k),  pb + k);
    }
    {   // negatives: 32*129*4 = 16512 B = 1032 x 16B; global row block is
        // b*16512 B from the base (16B multiple); smem dst at byte 1056 (16B mult)
        const char* src = (const char*)nb;
        const uint32_t dst = tw_s + 4u * OFF_NEG;
#pragma unroll 4
        for (int c = lane; c < 1032; c += 32)
            cpa16(dst + 16u * c, src + (size_t)16 * c);
    }
    asm volatile("cp.async.commit_group;");

    // independent gathers under the copy
    const int ai    = __ldg(aidx + b);
    const int colme = (lane == 0) ? __ldg(pidx + b) : __ldg(nidx + b * K_ + lane - 1);
    const int col32 = __ldg(nidx + b * K_ + 31);
    const float* __restrict__ trow = tree + (size_t)ai * V_;
    const float tme = __ldg(trow + colme);
    const float t32 = __ldg(trow + col32);

    asm volatile("cp.async.wait_group 0;" ::: "memory");
    __syncwarp();

    // ===== lane l computes item l's dot directly from smem =====
    // -lorentz_inner = a0*v0 - sum_{k>=1} a_k v_k = 2*a0*v0 - dot
    const float a0 = tw[0];
    const float* vrow = (lane == 0) ? (tw + OFF_POS)
                                    : (tw + OFF_NEG + (lane - 1) * D_);
    float dot = 0.0f;
#pragma unroll 4
    for (int k = 0; k < 128; k += 4) {
        dot = fmaf(tw[k],     vrow[k],     dot);
        dot = fmaf(tw[k + 1], vrow[k + 1], dot);
        dot = fmaf(tw[k + 2], vrow[k + 2], dot);
        dot = fmaf(tw[k + 3], vrow[k + 3], dot);
    }
    dot = fmaf(tw[128], vrow[128], dot);
    const float dsum = fmaf(2.0f * a0, vrow[0], -dot);

    // item 32 (negative #31): all lanes cooperate
    const float* v32 = tw + OFF_NEG + 31 * D_;
    float p32 = 0.0f;
#pragma unroll
    for (int k = lane; k < D_; k += 32) p32 = fmaf(tw[k], v32[k], p32);
    const float s32 = fmaf(2.0f * a0, v32[0], -warp_sum(p32));

    const float dme = acoshd(dsum);
    const float d32 = acoshd(s32);

    // ===== rel =====
    const float maxt   = fmaxf(warp_max(tme), t32);
    const float inv_mt = __fdividef(1.0f, maxt + 1e-6f);
    const float relme  = (maxt - tme + 1e-6f) * inv_mt;
    const float rel32  = (maxt - t32 + 1e-6f) * inv_mt;

    // ===== stable ranks via lane rotation =====
    int rank = 1;   // ascending rank of d (1-based)
    int rr   = 0;   // descending rank of rel (0-based)
#pragma unroll
    for (int o = 1; o < 32; o++) {
        const int j = (lane + o) & 31;
        const float dj = __shfl_sync(0xffffffffu, dme,   j);
        const float rj = __shfl_sync(0xffffffffu, relme, j);
        rank += (dj < dme)   || (dj == dme   && j < lane);
        rr   += (rj > relme) || (rj == relme && j < lane);
    }
    rank += (d32 < dme);
    rr   += (rel32 > relme);

    const int rank32 = 1 + (int)__reduce_add_sync(0xffffffffu, (unsigned)(dme <= d32));
    const int rr32   =     (int)__reduce_add_sync(0xffffffffu, (unsigned)(relme >= rel32));

    const float cme = (rank   <= KTOP) ? 1.0f / log2f((float)(rank   + 1)) : 0.0f;
    const float c32 = (rank32 <= KTOP) ? 1.0f / log2f((float)(rank32 + 1)) : 0.0f;

    float ic = (rr < KTOP) ? relme * __fdividef(1.0f, log2f((float)(rr + 2))) : 0.0f;
    if (lane == 0 && rr32 < KTOP) ic += rel32 * __fdividef(1.0f, log2f((float)(rr32 + 2)));
    const float idcg = warp_sum(ic);
    const float inv_idcg = (idcg > 0.0f) ? __fdividef(1.0f, idcg) : 0.0f;

    // ===== pairwise lambda: rotation covers C(32,2); o=16 double-counted =====
    float acc = 0.0f;
#pragma unroll
    for (int o = 1; o <= 16; o++) {
        const int j = (lane + o) & 31;
        const float rj = __shfl_sync(0xffffffffu, relme, j);
        const float cj = __shfl_sync(0xffffffffu, cme,   j);
        const float dj = __shfl_sync(0xffffffffu, dme,   j);
        const float t  = pair_term(relme, cme, dme, rj, cj, dj, inv_idcg);
        acc += (o == 16) ? 0.5f * t : t;
    }
    acc += pair_term(relme, cme, dme, rel32, c32, d32, inv_idcg);

    acc = warp_sum(acc);
    if (lane == 0) s_warp[w] = acc;
    __syncthreads();

    if (threadIdx.x == 0) {
        float bsum = 0.0f;
#pragma unroll
        for (int i = 0; i < WARPS_PER_BLK; i++) bsum += s_warp[i];
        g_part[blockIdx.x] = bsum;
        __threadfence();
        const int prev = atomicAdd(&g_count, 1);
        s_last = (prev == BLOCKS - 1);
    }
    __syncthreads();

    if (s_last) {
        __threadfence();
        float v = 0.0f;
        for (int i = threadIdx.x; i < BLOCKS; i += 128) v += g_part[i];
        s_fin[threadIdx.x] = v;
        __syncthreads();
#pragma unroll
        for (int o = 64; o; o >>= 1) {
            if (threadIdx.x < o) s_fin[threadIdx.x] += s_fin[threadIdx.x + o];
            __syncthreads();
        }
        if (threadIdx.x == 0) {
            out[0] = WEIGHT_ * s_fin[0] / (float)B_;
            g_count = 0;
        }
    }
}

extern "C" void kernel_launch(void* const* d_in, const int* in_sizes, int n_in,
                              void* d_out, int out_size)
{
    const float* anchor   = (const float*)d_in[0];
    const float* positive = (const float*)d_in[1];
    const float* negative = (const float*)d_in[2];
    const float* tree     = (const float*)d_in[3];
    const int*   aidx     = (const int*)d_in[4];
    const int*   pidx     = (const int*)d_in[5];
    const int*   nidx     = (const int*)d_in[6];

    cudaFuncSetAttribute(lr_fused, cudaFuncAttributeMaxDynamicSharedMemorySize,
                         SMEM_BYTES);
    lr_fused<<<BLOCKS, 128, SMEM_BYTES>>>(anchor, positive, negative, tree,
                                          aidx, pidx, nidx, (float*)d_out);
}

// round 8
// speedup vs baseline: 1.4327x; 1.4327x over previous
#include <cuda_runtime.h>

constexpr int B_ = 8192;
constexpr int K_ = 32;
constexpr int D_ = 129;
constexpr int V_ = 2048;
constexpr int KTOP = 10;
constexpr float WEIGHT_ = 0.15f;
constexpr int WARPS_PER_BLK = 8;
constexpr int BLOCKS = B_ / WARPS_PER_BLK;   // 1024

__device__ float g_part[BLOCKS];
__device__ int   g_count = 0;

__device__ __forceinline__ float warp_sum(float v) {
#pragma unroll
    for (int o = 16; o; o >>= 1) v += __shfl_xor_sync(0xffffffffu, v, o);
    return v;
}
__device__ __forceinline__ float warp_max(float v) {
#pragma unroll
    for (int o = 16; o; o >>= 1) v = fmaxf(v, __shfl_xor_sync(0xffffffffu, v, o));
    return v;
}
__device__ __forceinline__ float acoshd(float x) {
    x = fmaxf(x, 1.0f + 1e-7f);
    return logf(x + sqrtf(x * x - 1.0f));
}
__device__ __forceinline__ float pair_term(float ri, float ci, float di,
                                           float rj, float cj, float dj,
                                           float inv_idcg) {
    float drel  = ri - rj;
    float delta = fabsf(drel * (ci - cj)) * inv_idcg;
    float dd    = dj - di;
    float s     = (drel > 0.0f) ? 1.0f : -1.0f;
    float x     = s * dd;
    float sig   = __fdividef(1.0f, 1.0f + __expf(-x));
    return s * delta * sig * (-dd);
}

// butterfly rounds m=8,4,2,1 on a 16-register tile
__device__ __forceinline__ void bfly_tail(float q[16], int lane) {
#pragma unroll
    for (int m = 8; m >= 1; m >>= 1) {
        const bool up = (lane & m) != 0;
#pragma unroll
        for (int t = 0; t < m; t++) {
            float send = up ? q[t] : q[t + m];
            float recv = __shfl_xor_sync(0xffffffffu, send, m);
            q[t] = (up ? q[t + m] : q[t]) + recv;
        }
    }
}

__global__ void __launch_bounds__(256, 5) lr_fused(
    const float* __restrict__ anchor,
    const float* __restrict__ positive,
    const float* __restrict__ negative,
    const float* __restrict__ tree,
    const int*   __restrict__ aidx,
    const int*   __restrict__ pidx,
    const int*   __restrict__ nidx,
    float*       __restrict__ out)
{
    __shared__ float s_warp[WARPS_PER_BLK];
    __shared__ float s_fin[256];
    __shared__ bool  s_last;

    const int w    = threadIdx.x >> 5;
    const int lane = threadIdx.x & 31;
    const int b    = blockIdx.x * WARPS_PER_BLK + w;

    const float* __restrict__ arow = anchor   + (size_t)b * D_;
    const float* __restrict__ pb   = positive + (size_t)b * D_;
    const float* __restrict__ nb   = negative + (size_t)b * K_ * D_;

    // start of dependent gather chain: issue first
    const int ai    = __ldg(aidx + b);
    const int colme = (lane == 0) ? __ldg(pidx + b) : __ldg(nidx + b * K_ + lane - 1);
    const int col32 = __ldg(nidx + b * K_ + 31);

    // anchor regs, sign-flipped for c>=1: sum(ah_c * v_c) = -lorentz_inner
    const float ah0 = (lane == 0) ? arow[0] : -arow[lane];
    const float ah1 = -arow[lane + 32];
    const float ah2 = -arow[lane + 64];
    const float ah3 = -arow[lane + 96];
    const float a128n = -arow[128];

    float q[16];

    // ===== group 1 loads: items 0..15 (item 0 = positive) =====
#pragma unroll
    for (int t = 0; t < 16; t++) {
        const float* v = (t == 0) ? pb : (nb + (t - 1) * D_);
        q[t] = fmaf(ah0, __ldcs(v + lane), fmaf(ah1, __ldcs(v + lane + 32),
               fmaf(ah2, __ldcs(v + lane + 64), ah3 * __ldcs(v + lane + 96))));
    }

    // second level of the gather chain, hidden under group-1 drain
    const float* __restrict__ trow = tree + (size_t)ai * V_;
    const float tme = __ldg(trow + colme);
    const float t32 = __ldg(trow + col32);

    // ===== butterfly 1: items 0..15 -> lanes 0..15 =====
    {
        const bool up = (lane & 16) != 0;
#pragma unroll
        for (int t = 0; t < 16; t++) {
            float recv = __shfl_xor_sync(0xffffffffu, q[t], 16);
            q[t] = up ? 0.0f : (q[t] + recv);
        }
    }
    bfly_tail(q, lane);
    const float r1 = q[0];              // lanes 0..15: item = lane

    // ===== group 2 loads: items 16..31 =====
#pragma unroll
    for (int t = 0; t < 16; t++) {
        const float* v = nb + (t + 15) * D_;
        q[t] = fmaf(ah0, __ldcs(v + lane), fmaf(ah1, __ldcs(v + lane + 32),
               fmaf(ah2, __ldcs(v + lane + 64), ah3 * __ldcs(v + lane + 96))));
    }

    // e128 tails + item-32 partial, issued under group-2 drain
    const float e128me  = __ldcs(((lane == 0) ? pb : (nb + (lane - 1) * D_)) + 128);
    const float e128_32 = __ldcs(nb + 31 * D_ + 128);
    float p32;
    {
        const float* v = nb + 31 * D_;
        p32 = fmaf(ah0, __ldcs(v + lane), fmaf(ah1, __ldcs(v + lane + 32),
              fmaf(ah2, __ldcs(v + lane + 64), ah3 * __ldcs(v + lane + 96))));
    }

    // ===== butterfly 2: items 16..31 -> lanes 16..31 =====
    {
        const bool up = (lane & 16) != 0;
#pragma unroll
        for (int t = 0; t < 16; t++) {
            float recv = __shfl_xor_sync(0xffffffffu, q[t], 16);
            q[t] = up ? (q[t] + recv) : 0.0f;
        }
    }
    bfly_tail(q, lane);

    float dsum = ((lane < 16) ? r1 : q[0]) + a128n * e128me;
    const float s32 = warp_sum(p32) + a128n * e128_32;

    const float dme = acoshd(dsum);
    const float d32 = acoshd(s32);

    // ===== rel =====
    const float maxt   = fmaxf(warp_max(tme), t32);
    const float inv_mt = __fdividef(1.0f, maxt + 1e-6f);
    const float relme  = (maxt - tme + 1e-6f) * inv_mt;
    const float rel32  = (maxt - t32 + 1e-6f) * inv_mt;

    // ===== stable ranks via lane rotation =====
    int rank = 1;   // ascending rank of d (1-based)
    int rr   = 0;   // descending rank of rel (0-based)
#pragma unroll
    for (int o = 1; o < 32; o++) {
        const int j = (lane + o) & 31;
        const float dj = __shfl_sync(0xffffffffu, dme,   j);
        const float rj = __shfl_sync(0xffffffffu, relme, j);
        rank += (dj < dme)   || (dj == dme   && j < lane);
        rr   += (rj > relme) || (rj == relme && j < lane);
    }
    rank += (d32 < dme);
    rr   += (rel32 > relme);

    const int rank32 = 1 + (int)__reduce_add_sync(0xffffffffu, (unsigned)(dme <= d32));
    const int rr32   =     (int)__reduce_add_sync(0xffffffffu, (unsigned)(relme >= rel32));

    const float cme = (rank   <= KTOP) ? 1.0f / log2f((float)(rank   + 1)) : 0.0f;
    const float c32 = (rank32 <= KTOP) ? 1.0f / log2f((float)(rank32 + 1)) : 0.0f;

    float ic = (rr < KTOP) ? relme * __fdividef(1.0f, log2f((float)(rr + 2))) : 0.0f;
    if (lane == 0 && rr32 < KTOP) ic += rel32 * __fdividef(1.0f, log2f((float)(rr32 + 2)));
    const float idcg = warp_sum(ic);
    const float inv_idcg = (idcg > 0.0f) ? __fdividef(1.0f, idcg) : 0.0f;

    // ===== pairwise lambda: rotation covers C(32,2); o=16 double-counted =====
    float acc = 0.0f;
#pragma unroll
    for (int o = 1; o <= 16; o++) {
        const int j = (lane + o) & 31;
        const float rj = __shfl_sync(0xffffffffu, relme, j);
        const float cj = __shfl_sync(0xffffffffu, cme,   j);
        const float dj = __shfl_sync(0xffffffffu, dme,   j);
        const float t  = pair_term(relme, cme, dme, rj, cj, dj, inv_idcg);
        acc += (o == 16) ? 0.5f * t : t;
    }
    acc += pair_term(relme, cme, dme, rel32, c32, d32, inv_idcg);

    acc = warp_sum(acc);
    if (lane == 0) s_warp[w] = acc;
    __syncthreads();

    if (threadIdx.x == 0) {
        float bsum = 0.0f;
#pragma unroll
        for (int i = 0; i < WARPS_PER_BLK; i++) bsum += s_warp[i];
        g_part[blockIdx.x] = bsum;
        __threadfence();
        const int prev = atomicAdd(&g_count, 1);
        s_last = (prev == BLOCKS - 1);
    }
    __syncthreads();

    if (s_last) {
        __threadfence();
        float v = 0.0f;
        for (int i = threadIdx.x; i < BLOCKS; i += 256) v += g_part[i];
        s_fin[threadIdx.x] = v;
        __syncthreads();
#pragma unroll
        for (int o = 128; o; o >>= 1) {
            if (threadIdx.x < o) s_fin[threadIdx.x] += s_fin[threadIdx.x + o];
            __syncthreads();
        }
        if (threadIdx.x == 0) {
            out[0] = WEIGHT_ * s_fin[0] / (float)B_;
            g_count = 0;
        }
    }
}

extern "C" void kernel_launch(void* const* d_in, const int* in_sizes, int n_in,
                              void* d_out, int out_size)
{
    const float* anchor   = (const float*)d_in[0];
    const float* positive = (const float*)d_in[1];
    const float* negative = (const float*)d_in[2];
    const float* tree     = (const float*)d_in[3];
    const int*   aidx     = (const int*)d_in[4];
    const int*   pidx     = (const int*)d_in[5];
    const int*   nidx     = (const int*)d_in[6];

    lr_fused<<<BLOCKS, 256>>>(anchor, positive, negative, tree,
                              aidx, pidx, nidx, (float*)d_out);
}

// round 9
// speedup vs baseline: 1.5969x; 1.1146x over previous
#include <cuda_runtime.h>

constexpr int B_ = 8192;
constexpr int K_ = 32;
constexpr int D_ = 129;
constexpr int V_ = 2048;
constexpr int KTOP = 10;
constexpr float WEIGHT_ = 0.15f;
constexpr int WARPS_PER_BLK = 8;
constexpr int BLOCKS = B_ / WARPS_PER_BLK;   // 1024

__device__ float g_part[BLOCKS];
__device__ int   g_count = 0;

__device__ __forceinline__ float warp_sum(float v) {
#pragma unroll
    for (int o = 16; o; o >>= 1) v += __shfl_xor_sync(0xffffffffu, v, o);
    return v;
}
__device__ __forceinline__ float warp_max(float v) {
#pragma unroll
    for (int o = 16; o; o >>= 1) v = fmaxf(v, __shfl_xor_sync(0xffffffffu, v, o));
    return v;
}
__device__ __forceinline__ float acoshd(float x) {
    x = fmaxf(x, 1.0f + 1e-7f);
    return logf(x + sqrtf(x * x - 1.0f));
}
__device__ __forceinline__ float pair_term(float ri, float ci, float di,
                                           float rj, float cj, float dj,
                                           float inv_idcg) {
    float drel  = ri - rj;
    float delta = fabsf(drel * (ci - cj)) * inv_idcg;
    float dd    = dj - di;
    float s     = (drel > 0.0f) ? 1.0f : -1.0f;
    float x     = s * dd;
    float sig   = __fdividef(1.0f, 1.0f + __expf(-x));
    return s * delta * sig * (-dd);
}

__global__ void __launch_bounds__(256, 4) lr_fused(
    const float* __restrict__ anchor,
    const float* __restrict__ positive,
    const float* __restrict__ negative,
    const float* __restrict__ tree,
    const int*   __restrict__ aidx,
    const int*   __restrict__ pidx,
    const int*   __restrict__ nidx,
    float*       __restrict__ out)
{
    __shared__ float s_warp[WARPS_PER_BLK];
    __shared__ float s_fin[256];
    __shared__ bool  s_last;

    const int w    = threadIdx.x >> 5;
    const int lane = threadIdx.x & 31;
    const int b    = blockIdx.x * WARPS_PER_BLK + w;

    const float* __restrict__ arow = anchor   + (size_t)b * D_;
    const float* __restrict__ pb   = positive + (size_t)b * D_;
    const float* __restrict__ nb   = negative + (size_t)b * K_ * D_;

    // dependent gather chain first
    const int ai    = __ldg(aidx + b);
    const int colme = (lane == 0) ? __ldg(pidx + b) : __ldg(nidx + b * K_ + lane - 1);
    const int col32 = __ldg(nidx + b * K_ + 31);

    // anchor regs, sign-flipped for c>=1: sum(ah_c * v_c) = -lorentz_inner
    const float ah0 = (lane == 0) ? arow[0] : -arow[lane];
    const float ah1 = -arow[lane + 32];
    const float ah2 = -arow[lane + 64];
    const float ah3 = -arow[lane + 96];
    const float a128n = -arow[128];

    // ===== single burst: all 32 item partials + item-32 partial =====
    float q[32];
#pragma unroll
    for (int t = 0; t < 32; t++) {
        const float* v = (t == 0) ? pb : (nb + (t - 1) * D_);
        q[t] = fmaf(ah0, __ldcs(v + lane), fmaf(ah1, __ldcs(v + lane + 32),
               fmaf(ah2, __ldcs(v + lane + 64), ah3 * __ldcs(v + lane + 96))));
    }
    float p32;
    {
        const float* v = nb + 31 * D_;
        p32 = fmaf(ah0, __ldcs(v + lane), fmaf(ah1, __ldcs(v + lane + 32),
              fmaf(ah2, __ldcs(v + lane + 64), ah3 * __ldcs(v + lane + 96))));
    }
    // ancillary loads issued under the burst
    const float* __restrict__ trow = tree + (size_t)ai * V_;
    const float tme = __ldg(trow + colme);
    const float t32 = __ldg(trow + col32);
    const float e128me  = __ldcs(((lane == 0) ? pb : (nb + (lane - 1) * D_)) + 128);
    const float e128_32 = __ldcs(nb + 31 * D_ + 128);

    // ===== full 5-round butterfly transpose-reduce: lane L ends with item L =====
#pragma unroll
    for (int m = 16; m >= 1; m >>= 1) {
        const bool up = (lane & m) != 0;
#pragma unroll
        for (int t = 0; t < m; t++) {
            float send = up ? q[t] : q[t + m];
            float recv = __shfl_xor_sync(0xffffffffu, send, m);
            q[t] = (up ? q[t + m] : q[t]) + recv;
        }
    }
    const float dsum = q[0] + a128n * e128me;
    const float s32  = warp_sum(p32) + a128n * e128_32;

    const float dme = acoshd(dsum);
    const float d32 = acoshd(s32);

    // ===== rel =====
    const float maxt   = fmaxf(warp_max(tme), t32);
    const float inv_mt = __fdividef(1.0f, maxt + 1e-6f);
    const float relme  = (maxt - tme + 1e-6f) * inv_mt;
    const float rel32  = (maxt - t32 + 1e-6f) * inv_mt;

    // ===== stable ranks via lane rotation =====
    int rank = 1;   // ascending rank of d (1-based)
    int rr   = 0;   // descending rank of rel (0-based)
#pragma unroll
    for (int o = 1; o < 32; o++) {
        const int j = (lane + o) & 31;
        const float dj = __shfl_sync(0xffffffffu, dme,   j);
        const float rj = __shfl_sync(0xffffffffu, relme, j);
        rank += (dj < dme)   || (dj == dme   && j < lane);
        rr   += (rj > relme) || (rj == relme && j < lane);
    }
    rank += (d32 < dme);
    rr   += (rel32 > relme);

    const int rank32 = 1 + (int)__reduce_add_sync(0xffffffffu, (unsigned)(dme <= d32));
    const int rr32   =     (int)__reduce_add_sync(0xffffffffu, (unsigned)(relme >= rel32));

    const float cme = (rank   <= KTOP) ? 1.0f / log2f((float)(rank   + 1)) : 0.0f;
    const float c32 = (rank32 <= KTOP) ? 1.0f / log2f((float)(rank32 + 1)) : 0.0f;

    float ic = (rr < KTOP) ? relme * __fdividef(1.0f, log2f((float)(rr + 2))) : 0.0f;
    if (lane == 0 && rr32 < KTOP) ic += rel32 * __fdividef(1.0f, log2f((float)(rr32 + 2)));
    const float idcg = warp_sum(ic);
    const float inv_idcg = (idcg > 0.0f) ? __fdividef(1.0f, idcg) : 0.0f;

    // ===== pairwise lambda: rotation covers C(32,2); o=16 double-counted =====
    float acc = 0.0f;
#pragma unroll
    for (int o = 1; o <= 16; o++) {
        const int j = (lane + o) & 31;
        const float rj = __shfl_sync(0xffffffffu, relme, j);
        const float cj = __shfl_sync(0xffffffffu, cme,   j);
        const float dj = __shfl_sync(0xffffffffu, dme,   j);
        const float t  = pair_term(relme, cme, dme, rj, cj, dj, inv_idcg);
        acc += (o == 16) ? 0.5f * t : t;
    }
    acc += pair_term(relme, cme, dme, rel32, c32, d32, inv_idcg);

    acc = warp_sum(acc);
    if (lane == 0) s_warp[w] = acc;
    __syncthreads();

    if (threadIdx.x == 0) {
        float bsum = 0.0f;
#pragma unroll
        for (int i = 0; i < WARPS_PER_BLK; i++) bsum += s_warp[i];
        g_part[blockIdx.x] = bsum;
        __threadfence();
        const int prev = atomicAdd(&g_count, 1);
        s_last = (prev == BLOCKS - 1);
    }
    __syncthreads();

    if (s_last) {
        __threadfence();
        float v = 0.0f;
        for (int i = threadIdx.x; i < BLOCKS; i += 256) v += g_part[i];
        s_fin[threadIdx.x] = v;
        __syncthreads();
#pragma unroll
        for (int o = 128; o; o >>= 1) {
            if (threadIdx.x < o) s_fin[threadIdx.x] += s_fin[threadIdx.x + o];
            __syncthreads();
        }
        if (threadIdx.x == 0) {
            out[0] = WEIGHT_ * s_fin[0] / (float)B_;
            g_count = 0;
        }
    }
}

extern "C" void kernel_launch(void* const* d_in, const int* in_sizes, int n_in,
                              void* d_out, int out_size)
{
    const float* anchor   = (const float*)d_in[0];
    const float* positive = (const float*)d_in[1];
    const float* negative = (const float*)d_in[2];
    const float* tree     = (const float*)d_in[3];
    const int*   aidx     = (const int*)d_in[4];
    const int*   pidx     = (const int*)d_in[5];
    const int*   nidx     = (const int*)d_in[6];

    lr_fused<<<BLOCKS, 256>>>(anchor, positive, negative, tree,
                              aidx, pidx, nidx, (float*)d_out);
}

// round 10
// speedup vs baseline: 1.6202x; 1.0145x over previous
#include <cuda_runtime.h>

constexpr int B_ = 8192;
constexpr int K_ = 32;
constexpr int D_ = 129;
constexpr int V_ = 2048;
constexpr int KTOP = 10;
constexpr float WEIGHT_ = 0.15f;
constexpr int WARPS_PER_BLK = 8;
constexpr int BLOCKS = B_ / WARPS_PER_BLK;   // 1024

__device__ float g_part[BLOCKS];
__device__ int   g_count = 0;

__device__ __forceinline__ float warp_sum(float v) {
#pragma unroll
    for (int o = 16; o; o >>= 1) v += __shfl_xor_sync(0xffffffffu, v, o);
    return v;
}
__device__ __forceinline__ float warp_max(float v) {
#pragma unroll
    for (int o = 16; o; o >>= 1) v = fmaxf(v, __shfl_xor_sync(0xffffffffu, v, o));
    return v;
}
// fast arccosh: MUFU-based log; rel-err budget is 1e-3, this is ~1e-6
__device__ __forceinline__ float acoshd(float x) {
    x = fmaxf(x, 1.0f + 1e-7f);
    return __logf(x + sqrtf(fmaf(x, x, -1.0f)));
}
__device__ __forceinline__ float inv_log2(float n) {   // 1/log2(n), n >= 2
    return __fdividef(1.0f, __log2f(n));
}
__device__ __forceinline__ float pair_term(float ri, float ci, float di,
                                           float rj, float cj, float dj,
                                           float inv_idcg) {
    float drel  = ri - rj;
    float delta = fabsf(drel * (ci - cj)) * inv_idcg;
    float dd    = dj - di;
    float s     = (drel > 0.0f) ? 1.0f : -1.0f;
    float x     = s * dd;
    float sig   = __fdividef(1.0f, 1.0f + __expf(-x));
    return s * delta * sig * (-dd);
}

__global__ void __launch_bounds__(256, 4) lr_fused(
    const float* __restrict__ anchor,
    const float* __restrict__ positive,
    const float* __restrict__ negative,
    const float* __restrict__ tree,
    const int*   __restrict__ aidx,
    const int*   __restrict__ pidx,
    const int*   __restrict__ nidx,
    float*       __restrict__ out)
{
    __shared__ float s_warp[WARPS_PER_BLK];
    __shared__ float s_fin[256];
    __shared__ bool  s_last;

    const int w    = threadIdx.x >> 5;
    const int lane = threadIdx.x & 31;
    const int b    = blockIdx.x * WARPS_PER_BLK + w;

    const float* __restrict__ arow = anchor   + (size_t)b * D_;
    const float* __restrict__ pb   = positive + (size_t)b * D_;
    const float* __restrict__ nb   = negative + (size_t)b * K_ * D_;

    // dependent gather chain first
    const int ai    = __ldg(aidx + b);
    const int colme = (lane == 0) ? __ldg(pidx + b) : __ldg(nidx + b * K_ + lane - 1);
    const int col32 = __ldg(nidx + b * K_ + 31);

    // anchor regs, sign-flipped for c>=1: sum(ah_c * v_c) = -lorentz_inner
    const float ah0 = (lane == 0) ? arow[0] : -arow[lane];
    const float ah1 = -arow[lane + 32];
    const float ah2 = -arow[lane + 64];
    const float ah3 = -arow[lane + 96];
    const float a128n = -arow[128];

    // ===== single burst: all 32 item partials + item-32 partial =====
    float q[32];
#pragma unroll
    for (int t = 0; t < 32; t++) {
        const float* v = (t == 0) ? pb : (nb + (t - 1) * D_);
        q[t] = fmaf(ah0, __ldcs(v + lane), fmaf(ah1, __ldcs(v + lane + 32),
               fmaf(ah2, __ldcs(v + lane + 64), ah3 * __ldcs(v + lane + 96))));
    }
    float p32;
    {
        const float* v = nb + 31 * D_;
        p32 = fmaf(ah0, __ldcs(v + lane), fmaf(ah1, __ldcs(v + lane + 32),
              fmaf(ah2, __ldcs(v + lane + 64), ah3 * __ldcs(v + lane + 96))));
    }
    // ancillary loads issued under the burst
    const float* __restrict__ trow = tree + (size_t)ai * V_;
    const float tme = __ldg(trow + colme);
    const float t32 = __ldg(trow + col32);
    const float e128me  = __ldcs(((lane == 0) ? pb : (nb + (lane - 1) * D_)) + 128);
    const float e128_32 = __ldcs(nb + 31 * D_ + 128);

    // ===== full 5-round butterfly transpose-reduce: lane L ends with item L =====
#pragma unroll
    for (int m = 16; m >= 1; m >>= 1) {
        const bool up = (lane & m) != 0;
#pragma unroll
        for (int t = 0; t < m; t++) {
            float send = up ? q[t] : q[t + m];
            float recv = __shfl_xor_sync(0xffffffffu, send, m);
            q[t] = (up ? q[t + m] : q[t]) + recv;
        }
    }
    const float dsum = q[0] + a128n * e128me;
    const float s32  = warp_sum(p32) + a128n * e128_32;

    const float dme = acoshd(dsum);
    const float d32 = acoshd(s32);

    // ===== rel =====
    const float maxt   = fmaxf(warp_max(tme), t32);
    const float inv_mt = __fdividef(1.0f, maxt + 1e-6f);
    const float relme  = (maxt - tme + 1e-6f) * inv_mt;
    const float rel32  = (maxt - t32 + 1e-6f) * inv_mt;

    // ===== stable ranks via lane rotation =====
    int rank = 1;   // ascending rank of d (1-based)
    int rr   = 0;   // descending rank of rel (0-based)
#pragma unroll
    for (int o = 1; o < 32; o++) {
        const int j = (lane + o) & 31;
        const float dj = __shfl_sync(0xffffffffu, dme,   j);
        const float rj = __shfl_sync(0xffffffffu, relme, j);
        rank += (dj < dme)   || (dj == dme   && j < lane);
        rr   += (rj > relme) || (rj == relme && j < lane);
    }
    rank += (d32 < dme);
    rr   += (rel32 > relme);

    const int rank32 = 1 + (int)__reduce_add_sync(0xffffffffu, (unsigned)(dme <= d32));
    const int rr32   =     (int)__reduce_add_sync(0xffffffffu, (unsigned)(relme >= rel32));

    const float cme = (rank   <= KTOP) ? inv_log2((float)(rank   + 1)) : 0.0f;
    const float c32 = (rank32 <= KTOP) ? inv_log2((float)(rank32 + 1)) : 0.0f;

    float ic = (rr < KTOP) ? relme * inv_log2((float)(rr + 2)) : 0.0f;
    if (lane == 0 && rr32 < KTOP) ic += rel32 * inv_log2((float)(rr32 + 2));
    const float idcg = warp_sum(ic);
    const float inv_idcg = (idcg > 0.0f) ? __fdividef(1.0f, idcg) : 0.0f;

    // ===== pairwise lambda: rotation covers C(32,2); o=16 double-counted =====
    float acc = 0.0f;
#pragma unroll
    for (int o = 1; o <= 16; o++) {
        const int j = (lane + o) & 31;
        const float rj = __shfl_sync(0xffffffffu, relme, j);
        const float cj = __shfl_sync(0xffffffffu, cme,   j);
        const float dj = __shfl_sync(0xffffffffu, dme,   j);
        const float t  = pair_term(relme, cme, dme, rj, cj, dj, inv_idcg);
        acc += (o == 16) ? 0.5f * t : t;
    }
    acc += pair_term(relme, cme, dme, rel32, c32, d32, inv_idcg);

    acc = warp_sum(acc);
    if (lane == 0) s_warp[w] = acc;
    __syncthreads();

    if (threadIdx.x == 0) {
        float bsum = 0.0f;
#pragma unroll
        for (int i = 0; i < WARPS_PER_BLK; i++) bsum += s_warp[i];
        g_part[blockIdx.x] = bsum;
        __threadfence();
        const int prev = atomicAdd(&g_count, 1);
        s_last = (prev == BLOCKS - 1);
    }
    __syncthreads();

    if (s_last) {
        __threadfence();
        float v = 0.0f;
        for (int i = threadIdx.x; i < BLOCKS; i += 256) v += g_part[i];
        s_fin[threadIdx.x] = v;
        __syncthreads();
#pragma unroll
        for (int o = 128; o; o >>= 1) {
            if (threadIdx.x < o) s_fin[threadIdx.x] += s_fin[threadIdx.x + o];
            __syncthreads();
        }
        if (threadIdx.x == 0) {
            out[0] = WEIGHT_ * s_fin[0] / (float)B_;
            g_count = 0;
        }
    }
}

extern "C" void kernel_launch(void* const* d_in, const int* in_sizes, int n_in,
                              void* d_out, int out_size)
{
    const float* anchor   = (const float*)d_in[0];
    const float* positive = (const float*)d_in[1];
    const float* negative = (const float*)d_in[2];
    const float* tree     = (const float*)d_in[3];
    const int*   aidx     = (const int*)d_in[4];
    const int*   pidx     = (const int*)d_in[5];
    const int*   nidx     = (const int*)d_in[6];

    lr_fused<<<BLOCKS, 256>>>(anchor, positive, negative, tree,
                              aidx, pidx, nidx, (float*)d_out);
}